// round 1
// baseline (speedup 1.0000x reference)
#include <cuda_runtime.h>
#include <cuda_bf16.h>
#include <cstdint>

#define B_  4096
#define N_  49
#define C_  256
#define H_  8
#define HD_ 32
#define NW_ 64
#define M_TOTAL (B_ * N_)          // 200704
#define SZ_QKV ((size_t)B_ * H_ * N_ * HD_)   // 51,380,224 elems per tensor
#define SZ_AO  ((size_t)B_ * N_ * C_)         // 51,380,224 elems per path

#define SCALE_F 0.17677669529663687f  // 32^-0.5

// Scratch (device globals — no runtime allocation allowed)
// layout: [stream(2)][which(3: q,k,v)][b][h][n][d]
__device__ float g_qkv[2 * 3 * SZ_QKV];
// layout: [path(2)][b][n][c]  (attention output pre-projection)
__device__ float g_ao[2 * SZ_AO];

// ---------------------------------------------------------------------------
// Kernel 1: QKV projection for both streams.
// GEMM: A[M_TOTAL,256] @ W[256,768] + bias, scatter into g_qkv.
// Tile 64x64x16, 256 threads, 4x4 register blocking.
// ---------------------------------------------------------------------------
__global__ __launch_bounds__(256) void qkv_gemm(
    const float* __restrict__ x, const float* __restrict__ rgb,
    const float* __restrict__ w0, const float* __restrict__ b0,
    const float* __restrict__ w1, const float* __restrict__ b1)
{
    const int stream = blockIdx.z;
    const float* __restrict__ A    = stream ? rgb : x;
    const float* __restrict__ W    = stream ? w1  : w0;
    const float* __restrict__ bias = stream ? b1  : b0;
    const int bm = blockIdx.y * 64;
    const int bn = blockIdx.x * 64;

    __shared__ float As[16][65];
    __shared__ float Bs[16][64];

    const int tid = threadIdx.x;
    const int tx = tid & 15, ty = tid >> 4;

    float acc[4][4] = {};

    for (int k0 = 0; k0 < 256; k0 += 16) {
        #pragma unroll
        for (int e = 0; e < 4; e++) {
            int lin = tid + e * 256;
            int m = lin >> 4, kk = lin & 15;
            As[kk][m] = A[(size_t)(bm + m) * 256 + k0 + kk];
        }
        #pragma unroll
        for (int e = 0; e < 4; e++) {
            int lin = tid + e * 256;
            int kk = lin >> 6, n = lin & 63;
            Bs[kk][n] = W[(size_t)(k0 + kk) * 768 + bn + n];
        }
        __syncthreads();
        #pragma unroll
        for (int kk = 0; kk < 16; kk++) {
            float a[4], bb[4];
            #pragma unroll
            for (int i = 0; i < 4; i++) a[i] = As[kk][ty * 4 + i];
            #pragma unroll
            for (int j = 0; j < 4; j++) bb[j] = Bs[kk][tx * 4 + j];
            #pragma unroll
            for (int i = 0; i < 4; i++)
                #pragma unroll
                for (int j = 0; j < 4; j++)
                    acc[i][j] += a[i] * bb[j];
        }
        __syncthreads();
    }

    #pragma unroll
    for (int i = 0; i < 4; i++) {
        int m = bm + ty * 4 + i;
        int wb = m / N_, wn = m - wb * N_;
        #pragma unroll
        for (int j = 0; j < 4; j++) {
            int col = bn + tx * 4 + j;
            float val = acc[i][j] + bias[col];
            int which = col >> 8;          // 0=q, 1=k, 2=v
            int r = col & 255;
            int h = r >> 5, d = r & 31;
            if (which == 0) val *= SCALE_F;
            size_t off = ((((size_t)(stream * 3 + which) * B_ + wb) * H_ + h)
                          * (size_t)(N_ * HD_)) + (size_t)wn * HD_ + d;
            g_qkv[off] = val;
        }
    }
}

// ---------------------------------------------------------------------------
// Kernel 2: fused attention per (window b, head h, path p).
// p=0 (xo):  q from rgb stream, k/v from x stream.
// p=1 (ro):  q from x stream,  k/v from rgb stream.
// S = q k^T + bias_table[rel_idx]+ mask[b%64]; softmax; O = S v.
// ---------------------------------------------------------------------------
__global__ __launch_bounds__(256) void attn_kernel(
    const float* __restrict__ mask, const float* __restrict__ bias_table,
    const int* __restrict__ rel_idx)
{
    const int b = blockIdx.x, h = blockIdx.y, p = blockIdx.z;
    const int qs = p ^ 1;   // q stream
    const int kvs = p;      // k/v stream

    const size_t base_q = (((size_t)(qs * 3 + 0) * B_ + b) * H_ + h) * (size_t)(N_ * HD_);
    const size_t base_k = (((size_t)(kvs * 3 + 1) * B_ + b) * H_ + h) * (size_t)(N_ * HD_);
    const size_t base_v = (((size_t)(kvs * 3 + 2) * B_ + b) * H_ + h) * (size_t)(N_ * HD_);

    __shared__ float sq[N_ * HD_];
    __shared__ float sk[N_ * HD_];
    __shared__ float sv[N_ * HD_];
    __shared__ float S[N_ * N_];

    const int tid = threadIdx.x;
    for (int i = tid; i < N_ * HD_; i += 256) {
        sq[i] = g_qkv[base_q + i];
        sk[i] = g_qkv[base_k + i];
        sv[i] = g_qkv[base_v + i];
    }
    __syncthreads();

    const float* __restrict__ mrow = mask + (size_t)(b & (NW_ - 1)) * (N_ * N_);
    for (int idx = tid; idx < N_ * N_; idx += 256) {
        int i = idx / N_, j = idx - i * N_;
        const float* qp = &sq[i * HD_];
        const float* kp = &sk[j * HD_];
        float s = 0.f;
        #pragma unroll
        for (int d = 0; d < HD_; d++) s += qp[d] * kp[d];
        s += bias_table[rel_idx[idx] * H_ + h] + mrow[idx];
        S[idx] = s;
    }
    __syncthreads();

    if (tid < N_) {
        float* row = &S[tid * N_];
        float mx = row[0];
        #pragma unroll
        for (int j = 1; j < N_; j++) mx = fmaxf(mx, row[j]);
        float sum = 0.f;
        #pragma unroll
        for (int j = 0; j < N_; j++) { float e = __expf(row[j] - mx); row[j] = e; sum += e; }
        float inv = 1.f / sum;
        #pragma unroll
        for (int j = 0; j < N_; j++) row[j] *= inv;
    }
    __syncthreads();

    for (int idx = tid; idx < N_ * HD_; idx += 256) {
        int i = idx >> 5, d = idx & 31;
        float o = 0.f;
        #pragma unroll
        for (int j = 0; j < N_; j++) o += S[i * N_ + j] * sv[j * HD_ + d];
        size_t off = ((size_t)p * B_ * N_ + (size_t)b * N_ + i) * (size_t)C_ + h * HD_ + d;
        g_ao[off] = o;
    }
}

// ---------------------------------------------------------------------------
// Kernel 3: output projection. g_ao[p] @ Wp[256,256] + bp -> d_out[p].
// Same 64x64x16 tiling.
// ---------------------------------------------------------------------------
__global__ __launch_bounds__(256) void proj_gemm(
    const float* __restrict__ w0, const float* __restrict__ b0,
    const float* __restrict__ w1, const float* __restrict__ b1,
    float* __restrict__ out)
{
    const int p = blockIdx.z;
    const float* __restrict__ A    = &g_ao[(size_t)p * SZ_AO];
    const float* __restrict__ W    = p ? w1 : w0;
    const float* __restrict__ bias = p ? b1 : b0;
    float* __restrict__ O = out + (size_t)p * SZ_AO;

    const int bm = blockIdx.y * 64;
    const int bn = blockIdx.x * 64;

    __shared__ float As[16][65];
    __shared__ float Bs[16][64];

    const int tid = threadIdx.x;
    const int tx = tid & 15, ty = tid >> 4;

    float acc[4][4] = {};

    for (int k0 = 0; k0 < 256; k0 += 16) {
        #pragma unroll
        for (int e = 0; e < 4; e++) {
            int lin = tid + e * 256;
            int m = lin >> 4, kk = lin & 15;
            As[kk][m] = A[(size_t)(bm + m) * 256 + k0 + kk];
        }
        #pragma unroll
        for (int e = 0; e < 4; e++) {
            int lin = tid + e * 256;
            int kk = lin >> 6, n = lin & 63;
            Bs[kk][n] = W[(size_t)(k0 + kk) * 256 + bn + n];
        }
        __syncthreads();
        #pragma unroll
        for (int kk = 0; kk < 16; kk++) {
            float a[4], bb[4];
            #pragma unroll
            for (int i = 0; i < 4; i++) a[i] = As[kk][ty * 4 + i];
            #pragma unroll
            for (int j = 0; j < 4; j++) bb[j] = Bs[kk][tx * 4 + j];
            #pragma unroll
            for (int i = 0; i < 4; i++)
                #pragma unroll
                for (int j = 0; j < 4; j++)
                    acc[i][j] += a[i] * bb[j];
        }
        __syncthreads();
    }

    #pragma unroll
    for (int i = 0; i < 4; i++) {
        int m = bm + ty * 4 + i;
        #pragma unroll
        for (int j = 0; j < 4; j++) {
            int col = bn + tx * 4 + j;
            O[(size_t)m * 256 + col] = acc[i][j] + bias[col];
        }
    }
}

// ---------------------------------------------------------------------------
// Host launcher
// inputs: 0 x, 1 rgb, 2 mask, 3 w_qkv, 4 b_qkv, 5 w_qkv_rgb, 6 b_qkv_rgb,
//         7 bias_table, 8 w_proj, 9 b_proj, 10 w_proj_rgb, 11 b_proj_rgb,
//         12 rel_idx (int32)
// output: concat(xo, ro) fp32, 2*B_*N_*C_ elements
// ---------------------------------------------------------------------------
extern "C" void kernel_launch(void* const* d_in, const int* in_sizes, int n_in,
                              void* d_out, int out_size)
{
    const float* x          = (const float*)d_in[0];
    const float* rgb        = (const float*)d_in[1];
    const float* mask       = (const float*)d_in[2];
    const float* w_qkv      = (const float*)d_in[3];
    const float* b_qkv      = (const float*)d_in[4];
    const float* w_qkv_rgb  = (const float*)d_in[5];
    const float* b_qkv_rgb  = (const float*)d_in[6];
    const float* bias_table = (const float*)d_in[7];
    const float* w_proj     = (const float*)d_in[8];
    const float* b_proj     = (const float*)d_in[9];
    const float* w_proj_rgb = (const float*)d_in[10];
    const float* b_proj_rgb = (const float*)d_in[11];
    const int*   rel_idx    = (const int*)d_in[12];
    float* out = (float*)d_out;

    dim3 g1(768 / 64, M_TOTAL / 64, 2);   // (12, 3136, 2)
    qkv_gemm<<<g1, 256>>>(x, rgb, w_qkv, b_qkv, w_qkv_rgb, b_qkv_rgb);

    dim3 g2(B_, H_, 2);                   // (4096, 8, 2)
    attn_kernel<<<g2, 256>>>(mask, bias_table, rel_idx);

    dim3 g3(256 / 64, M_TOTAL / 64, 2);   // (4, 3136, 2)
    proj_gemm<<<g3, 256>>>(w_proj, b_proj, w_proj_rgb, b_proj_rgb, out);
}

// round 3
// speedup vs baseline: 1.4128x; 1.4128x over previous
#include <cuda_runtime.h>
#include <cuda_bf16.h>
#include <cstdint>

#define B_  4096
#define N_  49
#define C_  256
#define H_  8
#define HD_ 32
#define NW_ 64
#define MT  (B_ * N_)              // 200704 rows
#define KS  768                    // split-K (3 * 256)
#define SZ_AO ((size_t)MT * C_)

#define SCALE_F 0.17677669529663687f

// ---------------- scratch (device globals; no runtime alloc) ----------------
__device__ __nv_bfloat16 g_A[2][(size_t)MT * KS];       // split input  [hi,hi,lo]
__device__ __nv_bfloat16 g_Wqkv[2][768 * KS];           // Wt[n][k]     [hi,lo,hi]
__device__ __nv_bfloat16 g_Wproj[2][256 * KS];
__device__ float         g_lin[2][(size_t)MT * 768];    // qkv linear out (q|k|v)
__device__ __nv_bfloat16 g_aob[2][(size_t)MT * KS];     // attn out, split [hi,hi,lo]

// ---------------- HMMA GEMM config ----------------
#define BM 128
#define BN 128
#define BK 32
#define STRIDE 40                   // bf16 elems per smem row (pad: conflict-free frags)
#define NCHUNK (KS / BK)            // 24

__device__ __forceinline__ void cp16(uint32_t dst, const void* src) {
    asm volatile("cp.async.cg.shared.global [%0], [%1], 16;" :: "r"(dst), "l"(src));
}
__device__ __forceinline__ void cp_commit() {
    asm volatile("cp.async.commit_group;" ::: "memory");
}
template<int NN> __device__ __forceinline__ void cp_wait() {
    asm volatile("cp.async.wait_group %0;" :: "n"(NN) : "memory");
}

__device__ __forceinline__ void mma16816(float* d, const uint32_t* a, const uint32_t* b) {
    asm volatile(
        "mma.sync.aligned.m16n8k16.row.col.f32.bf16.bf16.f32 "
        "{%0,%1,%2,%3}, {%4,%5,%6,%7}, {%8,%9}, {%0,%1,%2,%3};"
        : "+f"(d[0]), "+f"(d[1]), "+f"(d[2]), "+f"(d[3])
        : "r"(a[0]), "r"(a[1]), "r"(a[2]), "r"(a[3]), "r"(b[0]), "r"(b[1]));
}

// Shared GEMM mainloop: acc[mt][nt][4] over K=768.
// A row-major [*,768], Wt row-major [n][768]. Warp tile 64x32, CTA 128x128.
struct SmemBuf {
    __nv_bfloat16 a[2][BM * STRIDE];
    __nv_bfloat16 b[2][BN * STRIDE];
};

__device__ __forceinline__ void gemm_main(
    SmemBuf* sm,
    const __nv_bfloat16* __restrict__ A, const __nv_bfloat16* __restrict__ Wt,
    int bm, int bn, float acc[4][4][4])
{
    const int tid  = threadIdx.x;
    const int lane = tid & 31;
    const int grow = tid >> 2;      // 0..63
    const int gcol = tid & 3;       // 16B group within 64B chunk row

    const uint32_t sa0 = (uint32_t)__cvta_generic_to_shared(sm->a[0]);
    const uint32_t sa1 = (uint32_t)__cvta_generic_to_shared(sm->a[1]);
    const uint32_t sb0 = (uint32_t)__cvta_generic_to_shared(sm->b[0]);
    const uint32_t sb1 = (uint32_t)__cvta_generic_to_shared(sm->b[1]);

    const __nv_bfloat16* Abase = A  + (size_t)bm * KS;
    const __nv_bfloat16* Bbase = Wt + (size_t)bn * KS;

    auto load_stage = [&](int c, int buf) {
        const uint32_t sa = buf ? sa1 : sa0;
        const uint32_t sb = buf ? sb1 : sb0;
        const int k0 = c * BK;
        #pragma unroll
        for (int i = 0; i < 2; i++) {
            int r = grow + i * 64;
            cp16(sa + (uint32_t)(r * STRIDE + gcol * 8) * 2,
                 Abase + (size_t)r * KS + k0 + gcol * 8);
            cp16(sb + (uint32_t)(r * STRIDE + gcol * 8) * 2,
                 Bbase + (size_t)r * KS + k0 + gcol * 8);
        }
        cp_commit();
    };

    const int wm = (tid >> 5) & 1;       // 2 warps along M
    const int wn = (tid >> 6);           // 4 warps along N
    const int fr = lane >> 2;            // 0..7
    const int fq = (lane & 3) * 2;       // 0,2,4,6

    load_stage(0, 0);

    for (int c = 0; c < NCHUNK; c++) {
        const int buf = c & 1;
        if (c + 1 < NCHUNK) load_stage(c + 1, buf ^ 1);
        if (c + 1 < NCHUNK) cp_wait<1>(); else cp_wait<0>();
        __syncthreads();

        const __nv_bfloat16* sA = sm->a[buf];
        const __nv_bfloat16* sB = sm->b[buf];

        #pragma unroll
        for (int ks = 0; ks < 2; ks++) {
            const int kb = ks * 16;
            uint32_t af[4][4], bf[4][2];
            #pragma unroll
            for (int mt = 0; mt < 4; mt++) {
                const __nv_bfloat16* p = &sA[(wm * 64 + mt * 16 + fr) * STRIDE + kb + fq];
                af[mt][0] = *(const uint32_t*)p;
                af[mt][1] = *(const uint32_t*)(p + 8 * STRIDE);
                af[mt][2] = *(const uint32_t*)(p + 8);
                af[mt][3] = *(const uint32_t*)(p + 8 * STRIDE + 8);
            }
            #pragma unroll
            for (int nt = 0; nt < 4; nt++) {
                const __nv_bfloat16* p = &sB[(wn * 32 + nt * 8 + fr) * STRIDE + kb + fq];
                bf[nt][0] = *(const uint32_t*)p;
                bf[nt][1] = *(const uint32_t*)(p + 8);
            }
            #pragma unroll
            for (int mt = 0; mt < 4; mt++)
                #pragma unroll
                for (int nt = 0; nt < 4; nt++)
                    mma16816(acc[mt][nt], af[mt], bf[nt]);
        }
        __syncthreads();
    }
}

// ---------------- GEMM kernels ----------------
__global__ __launch_bounds__(256) void qkv_hmma(
    const float* __restrict__ b0, const float* __restrict__ b1)
{
    __shared__ SmemBuf sm;
    const int stream = blockIdx.z;
    const int bn = blockIdx.x * BN;
    const int bm = blockIdx.y * BM;

    float acc[4][4][4] = {};
    gemm_main(&sm, g_A[stream], g_Wqkv[stream], bm, bn, acc);

    const float* __restrict__ bias = stream ? b1 : b0;
    float* __restrict__ O = g_lin[stream];
    const int lane = threadIdx.x & 31;
    const int wm = (threadIdx.x >> 5) & 1, wn = threadIdx.x >> 6;
    const float sc = (bn < 256) ? SCALE_F : 1.0f;

    #pragma unroll
    for (int mt = 0; mt < 4; mt++) {
        const int r = bm + wm * 64 + mt * 16 + (lane >> 2);
        #pragma unroll
        for (int nt = 0; nt < 4; nt++) {
            const int col = bn + wn * 32 + nt * 8 + (lane & 3) * 2;
            const float bx = bias[col], by = bias[col + 1];
            float2 v0 = { (acc[mt][nt][0] + bx) * sc, (acc[mt][nt][1] + by) * sc };
            float2 v1 = { (acc[mt][nt][2] + bx) * sc, (acc[mt][nt][3] + by) * sc };
            *(float2*)&O[(size_t)r * 768 + col]       = v0;
            *(float2*)&O[(size_t)(r + 8) * 768 + col] = v1;
        }
    }
}

__global__ __launch_bounds__(256) void proj_hmma(
    const float* __restrict__ bp0, const float* __restrict__ bp1,
    float* __restrict__ out)
{
    __shared__ SmemBuf sm;
    const int p = blockIdx.z;
    const int bn = blockIdx.x * BN;
    const int bm = blockIdx.y * BM;

    float acc[4][4][4] = {};
    gemm_main(&sm, g_aob[p], g_Wproj[p], bm, bn, acc);

    const float* __restrict__ bias = p ? bp1 : bp0;
    float* __restrict__ O = out + (size_t)p * SZ_AO;
    const int lane = threadIdx.x & 31;
    const int wm = (threadIdx.x >> 5) & 1, wn = threadIdx.x >> 6;

    #pragma unroll
    for (int mt = 0; mt < 4; mt++) {
        const int r = bm + wm * 64 + mt * 16 + (lane >> 2);
        #pragma unroll
        for (int nt = 0; nt < 4; nt++) {
            const int col = bn + wn * 32 + nt * 8 + (lane & 3) * 2;
            const float bx = bias[col], by = bias[col + 1];
            float2 v0 = { acc[mt][nt][0] + bx, acc[mt][nt][1] + by };
            float2 v1 = { acc[mt][nt][2] + bx, acc[mt][nt][3] + by };
            *(float2*)&O[(size_t)r * 256 + col]       = v0;
            *(float2*)&O[(size_t)(r + 8) * 256 + col] = v1;
        }
    }
}

// ---------------- conversion kernels ----------------
__global__ __launch_bounds__(256) void conv_in(
    const float* __restrict__ x, const float* __restrict__ rgb)
{
    const int s = blockIdx.y;
    const float* __restrict__ src = s ? rgb : x;
    size_t idx = (size_t)blockIdx.x * 256 + threadIdx.x;
    float v = src[idx];
    __nv_bfloat16 hi = __float2bfloat16(v);
    __nv_bfloat16 lo = __float2bfloat16(v - __bfloat162float(hi));
    size_t m = idx >> 8;
    int k = (int)(idx & 255);
    __nv_bfloat16* row = g_A[s] + m * KS;
    row[k] = hi; row[256 + k] = hi; row[512 + k] = lo;
}

__global__ __launch_bounds__(256) void conv_w(
    const float* __restrict__ w_qkv, const float* __restrict__ w_qkv_rgb,
    const float* __restrict__ w_proj, const float* __restrict__ w_proj_rgb)
{
    const int which = blockIdx.y;
    const float* src; __nv_bfloat16* dst; int NC;
    switch (which) {
        case 0: src = w_qkv;       dst = g_Wqkv[0];  NC = 768; break;
        case 1: src = w_qkv_rgb;   dst = g_Wqkv[1];  NC = 768; break;
        case 2: src = w_proj;      dst = g_Wproj[0]; NC = 256; break;
        default: src = w_proj_rgb; dst = g_Wproj[1]; NC = 256; break;
    }
    int idx = blockIdx.x * 256 + threadIdx.x;
    if (idx >= 256 * NC) return;
    int k = idx / NC, n = idx % NC;
    float v = src[idx];
    __nv_bfloat16 hi = __float2bfloat16(v);
    __nv_bfloat16 lo = __float2bfloat16(v - __bfloat162float(hi));
    __nv_bfloat16* row = dst + (size_t)n * KS;
    row[k] = hi; row[256 + k] = lo; row[512 + k] = hi;   // pairs A[hi,hi,lo]
}

// ---------------- fused attention (fp32) ----------------
__global__ __launch_bounds__(256) void attn_kernel(
    const float* __restrict__ mask, const float* __restrict__ bias_table,
    const int* __restrict__ rel_idx)
{
    const int b = blockIdx.x, h = blockIdx.y, p = blockIdx.z;
    const int qs = p ^ 1, kv = p;
    const float* __restrict__ qbase = g_lin[qs] + (size_t)b * N_ * 768 + h * HD_;
    const float* __restrict__ kbase = g_lin[kv] + (size_t)b * N_ * 768 + 256 + h * HD_;
    const float* __restrict__ vbase = g_lin[kv] + (size_t)b * N_ * 768 + 512 + h * HD_;

    __shared__ float sq[N_ * HD_], sk[N_ * HD_], sv[N_ * HD_], S[N_ * N_];
    const int tid = threadIdx.x;
    for (int i = tid; i < N_ * HD_; i += 256) {
        int n = i >> 5, d = i & 31;
        sq[i] = qbase[n * 768 + d];
        sk[i] = kbase[n * 768 + d];
        sv[i] = vbase[n * 768 + d];
    }
    __syncthreads();

    const float* __restrict__ mrow = mask + (size_t)(b & (NW_ - 1)) * (N_ * N_);
    for (int idx = tid; idx < N_ * N_; idx += 256) {
        int i = idx / N_, j = idx - i * N_;
        const float* qp = &sq[i * HD_];
        const float* kp = &sk[j * HD_];
        float s = 0.f;
        #pragma unroll
        for (int d = 0; d < HD_; d++) s += qp[d] * kp[d];
        s += bias_table[rel_idx[idx] * H_ + h] + mrow[idx];
        S[idx] = s;
    }
    __syncthreads();

    if (tid < N_) {
        float* row = &S[tid * N_];
        float mx = row[0];
        #pragma unroll
        for (int j = 1; j < N_; j++) mx = fmaxf(mx, row[j]);
        float sum = 0.f;
        #pragma unroll
        for (int j = 0; j < N_; j++) { float e = __expf(row[j] - mx); row[j] = e; sum += e; }
        float inv = 1.f / sum;
        #pragma unroll
        for (int j = 0; j < N_; j++) row[j] *= inv;
    }
    __syncthreads();

    for (int idx = tid; idx < N_ * HD_; idx += 256) {
        int i = idx >> 5, d = idx & 31;
        float o = 0.f;
        #pragma unroll
        for (int j = 0; j < N_; j++) o += S[i * N_ + j] * sv[j * HD_ + d];
        __nv_bfloat16 hi = __float2bfloat16(o);
        __nv_bfloat16 lo = __float2bfloat16(o - __bfloat162float(hi));
        __nv_bfloat16* row = g_aob[p] + ((size_t)b * N_ + i) * KS + h * HD_ + d;
        row[0] = hi; row[256] = hi; row[512] = lo;
    }
}

// ---------------- host launcher ----------------
extern "C" void kernel_launch(void* const* d_in, const int* in_sizes, int n_in,
                              void* d_out, int out_size)
{
    const float* x          = (const float*)d_in[0];
    const float* rgb        = (const float*)d_in[1];
    const float* mask       = (const float*)d_in[2];
    const float* w_qkv      = (const float*)d_in[3];
    const float* b_qkv      = (const float*)d_in[4];
    const float* w_qkv_rgb  = (const float*)d_in[5];
    const float* b_qkv_rgb  = (const float*)d_in[6];
    const float* bias_table = (const float*)d_in[7];
    const float* w_proj     = (const float*)d_in[8];
    const float* b_proj     = (const float*)d_in[9];
    const float* w_proj_rgb = (const float*)d_in[10];
    const float* b_proj_rgb = (const float*)d_in[11];
    const int*   rel_idx    = (const int*)d_in[12];
    float* out = (float*)d_out;

    conv_w<<<dim3(768, 4), 256>>>(w_qkv, w_qkv_rgb, w_proj, w_proj_rgb);
    conv_in<<<dim3(MT, 2), 256>>>(x, rgb);

    qkv_hmma<<<dim3(768 / BN, MT / BM, 2), 256>>>(b_qkv, b_qkv_rgb);

    attn_kernel<<<dim3(B_, H_, 2), 256>>>(mask, bias_table, rel_idx);

    proj_hmma<<<dim3(256 / BN, MT / BM, 2), 256>>>(b_proj, b_proj_rgb, out);
}

// round 4
// speedup vs baseline: 3.4541x; 2.4449x over previous
#include <cuda_runtime.h>
#include <cuda_fp16.h>
#include <cstdint>

#define B_  4096
#define N_  49
#define H_  8
#define NW_ 64
#define MT  (B_ * N_)              // 200704 rows
#define KSP 512                    // 2-term split K (2 * 256)
#define SZ_AO ((size_t)MT * 256)

#define SCALE_F 0.17677669529663687f

// ---------------- scratch (device globals; no runtime alloc) ----------------
__device__ __half g_A[2][(size_t)MT * KSP];     // input split [hi, lo] fp16
__device__ __half g_Wqkv[2][768 * 256];         // Wt[n][k] fp16 (single copy)
__device__ __half g_Wproj[2][256 * 256];
__device__ float  g_lin[2][(size_t)MT * 768];   // qkv linear out (q|k|v)
__device__ __half g_aob[2][(size_t)MT * KSP];   // attn out split [hi, lo]

// ---------------- GEMM config ----------------
#define BM 128
#define BN 128
#define SA_STR 40     // halves per A smem row (32 + 8 pad)
#define SB_STR 264    // halves per B smem row (256 + 8 pad)
#define NCH 16        // 512 / 32 k-chunks

struct GSmem {
    __align__(16) __half B[BN * SB_STR];        // 67584 B
    __align__(16) __half A[4][BM * SA_STR];     // 4 x 10240 B
};
#define SMEM_SZ ((int)sizeof(GSmem))

__device__ __forceinline__ void cp16(uint32_t dst, const void* src) {
    asm volatile("cp.async.cg.shared.global [%0], [%1], 16;" :: "r"(dst), "l"(src));
}
__device__ __forceinline__ void cp_commit() {
    asm volatile("cp.async.commit_group;" ::: "memory");
}
template<int NN> __device__ __forceinline__ void cp_wait() {
    asm volatile("cp.async.wait_group %0;" :: "n"(NN) : "memory");
}

__device__ __forceinline__ void mma16816(float* d, const uint32_t* a, const uint32_t* b) {
    asm volatile(
        "mma.sync.aligned.m16n8k16.row.col.f32.f16.f16.f32 "
        "{%0,%1,%2,%3}, {%4,%5,%6,%7}, {%8,%9}, {%0,%1,%2,%3};"
        : "+f"(d[0]), "+f"(d[1]), "+f"(d[2]), "+f"(d[3])
        : "r"(a[0]), "r"(a[1]), "r"(a[2]), "r"(a[3]), "r"(b[0]), "r"(b[1]));
}

// GEMM mainloop: D[128,128] tile at (bm, bn). A [M][512] fp16 split,
// W [n][256] fp16. B panel resident; A 4-stage cp.async pipeline.
__device__ __forceinline__ void gemm_main(
    GSmem& sm, const __half* __restrict__ A, const __half* __restrict__ W,
    int bm, int bn, float acc[4][4][4])
{
    const int tid = threadIdx.x;
    const uint32_t sB = (uint32_t)__cvta_generic_to_shared(sm.B);
    const uint32_t sA = (uint32_t)__cvta_generic_to_shared(sm.A);

    // B panel: 128 rows x 256 halves
    #pragma unroll
    for (int i = 0; i < 16; i++) {
        int idx = tid + i * 256;
        int r = idx >> 5, g = idx & 31;
        cp16(sB + (uint32_t)(r * SB_STR + g * 8) * 2,
             W + (size_t)(bn + r) * 256 + g * 8);
    }
    cp_commit();

    auto issueA = [&](int c) {
        uint32_t dst = sA + (uint32_t)((c & 3) * BM * SA_STR) * 2;
        #pragma unroll
        for (int i = 0; i < 2; i++) {
            int idx = tid + i * 256;
            int r = idx >> 2, g = idx & 3;
            cp16(dst + (uint32_t)(r * SA_STR + g * 8) * 2,
                 A + (size_t)(bm + r) * KSP + c * 32 + g * 8);
        }
        cp_commit();
    };
    issueA(0); issueA(1); issueA(2);

    const int lane = tid & 31;
    const int wm = (tid >> 5) & 1, wn = tid >> 6;
    const int fr = lane >> 2, fq = (lane & 3) * 2;

    auto compute = [&](int c) {
        const __half* a_s = sm.A[c & 3];
        const __half* b_s = sm.B + (c & 7) * 32;
        #pragma unroll
        for (int ks = 0; ks < 2; ks++) {
            const int kb = ks * 16;
            uint32_t af[4][4], bf[4][2];
            #pragma unroll
            for (int mt = 0; mt < 4; mt++) {
                const __half* p = &a_s[(wm * 64 + mt * 16 + fr) * SA_STR + kb + fq];
                af[mt][0] = *(const uint32_t*)p;
                af[mt][1] = *(const uint32_t*)(p + 8 * SA_STR);
                af[mt][2] = *(const uint32_t*)(p + 8);
                af[mt][3] = *(const uint32_t*)(p + 8 * SA_STR + 8);
            }
            #pragma unroll
            for (int nt = 0; nt < 4; nt++) {
                const __half* p = &b_s[(wn * 32 + nt * 8 + fr) * SB_STR + kb + fq];
                bf[nt][0] = *(const uint32_t*)p;
                bf[nt][1] = *(const uint32_t*)(p + 8);
            }
            #pragma unroll
            for (int mt = 0; mt < 4; mt++)
                #pragma unroll
                for (int nt = 0; nt < 4; nt++)
                    mma16816(acc[mt][nt], af[mt], bf[nt]);
        }
    };

    for (int c = 0; c < 13; c++) {
        cp_wait<2>();
        __syncthreads();
        issueA(c + 3);          // targets stage (c-1)&3 — freed by the sync
        compute(c);
    }
    cp_wait<2>(); __syncthreads(); compute(13);
    cp_wait<1>(); __syncthreads(); compute(14);
    cp_wait<0>(); __syncthreads(); compute(15);
}

// ---------------- GEMM kernels ----------------
__global__ __launch_bounds__(256, 2) void qkv_hmma(
    const float* __restrict__ b0, const float* __restrict__ b1)
{
    extern __shared__ char smem_raw[];
    GSmem& sm = *(GSmem*)smem_raw;
    const int stream = blockIdx.z;
    const int bn = blockIdx.x * BN;
    const int bm = blockIdx.y * BM;

    float acc[4][4][4] = {};
    gemm_main(sm, g_A[stream], g_Wqkv[stream], bm, bn, acc);

    const float* __restrict__ bias = stream ? b1 : b0;
    float* __restrict__ O = g_lin[stream];
    const int lane = threadIdx.x & 31;
    const int wm = (threadIdx.x >> 5) & 1, wn = threadIdx.x >> 6;
    const float sc = (bn < 256) ? SCALE_F : 1.0f;

    #pragma unroll
    for (int mt = 0; mt < 4; mt++) {
        const int r = bm + wm * 64 + mt * 16 + (lane >> 2);
        #pragma unroll
        for (int nt = 0; nt < 4; nt++) {
            const int col = bn + wn * 32 + nt * 8 + (lane & 3) * 2;
            const float bx = bias[col], by = bias[col + 1];
            float2 v0 = { (acc[mt][nt][0] + bx) * sc, (acc[mt][nt][1] + by) * sc };
            float2 v1 = { (acc[mt][nt][2] + bx) * sc, (acc[mt][nt][3] + by) * sc };
            *(float2*)&O[(size_t)r * 768 + col]       = v0;
            *(float2*)&O[(size_t)(r + 8) * 768 + col] = v1;
        }
    }
}

__global__ __launch_bounds__(256, 2) void proj_hmma(
    const float* __restrict__ bp0, const float* __restrict__ bp1,
    float* __restrict__ out)
{
    extern __shared__ char smem_raw[];
    GSmem& sm = *(GSmem*)smem_raw;
    const int p = blockIdx.z;
    const int bn = blockIdx.x * BN;
    const int bm = blockIdx.y * BM;

    float acc[4][4][4] = {};
    gemm_main(sm, g_aob[p], g_Wproj[p], bm, bn, acc);

    const float* __restrict__ bias = p ? bp1 : bp0;
    float* __restrict__ O = out + (size_t)p * SZ_AO;
    const int lane = threadIdx.x & 31;
    const int wm = (threadIdx.x >> 5) & 1, wn = threadIdx.x >> 6;

    #pragma unroll
    for (int mt = 0; mt < 4; mt++) {
        const int r = bm + wm * 64 + mt * 16 + (lane >> 2);
        #pragma unroll
        for (int nt = 0; nt < 4; nt++) {
            const int col = bn + wn * 32 + nt * 8 + (lane & 3) * 2;
            const float bx = bias[col], by = bias[col + 1];
            float2 v0 = { acc[mt][nt][0] + bx, acc[mt][nt][1] + by };
            float2 v1 = { acc[mt][nt][2] + bx, acc[mt][nt][3] + by };
            *(float2*)&O[(size_t)r * 256 + col]       = v0;
            *(float2*)&O[(size_t)(r + 8) * 256 + col] = v1;
        }
    }
}

// ---------------- conversion kernels ----------------
__global__ __launch_bounds__(256) void conv_in(
    const float* __restrict__ x, const float* __restrict__ rgb)
{
    const int s = blockIdx.y;
    const float* __restrict__ src = s ? rgb : x;
    const size_t m = blockIdx.x;
    const int k = threadIdx.x;
    float v = src[m * 256 + k];
    __half hi = __float2half_rn(v);
    __half lo = __float2half_rn(v - __half2float(hi));
    g_A[s][m * KSP + k] = hi;
    g_A[s][m * KSP + 256 + k] = lo;
}

__global__ __launch_bounds__(256) void conv_w(
    const float* __restrict__ w_qkv, const float* __restrict__ w_qkv_rgb,
    const float* __restrict__ w_proj, const float* __restrict__ w_proj_rgb)
{
    const int which = blockIdx.y;
    const float* src; __half* dst; int NC;
    switch (which) {
        case 0: src = w_qkv;       dst = g_Wqkv[0];  NC = 768; break;
        case 1: src = w_qkv_rgb;   dst = g_Wqkv[1];  NC = 768; break;
        case 2: src = w_proj;      dst = g_Wproj[0]; NC = 256; break;
        default: src = w_proj_rgb; dst = g_Wproj[1]; NC = 256; break;
    }
    int idx = blockIdx.x * 256 + threadIdx.x;
    if (idx >= 256 * NC) return;
    int k = idx / NC, n = idx % NC;
    dst[(size_t)n * 256 + k] = __float2half_rn(src[idx]);
}

// ---------------- fused attention (fp32, register-blocked) ----------------
__global__ __launch_bounds__(256) void attn_kernel(
    const float* __restrict__ mask, const float* __restrict__ bias_table,
    const int* __restrict__ rel_idx)
{
    const int b = blockIdx.x, h = blockIdx.y, p = blockIdx.z;
    const int qs = p ^ 1, kv = p;
    const float* __restrict__ qb = g_lin[qs] + (size_t)b * N_ * 768 + h * 32;
    const float* __restrict__ kb = g_lin[kv] + (size_t)b * N_ * 768 + 256 + h * 32;
    const float* __restrict__ vb = g_lin[kv] + (size_t)b * N_ * 768 + 512 + h * 32;

    __shared__ float qT[32 * 56];   // [d][n], padded
    __shared__ float kT[32 * 56];
    __shared__ float V[49 * 36];    // [n][d], padded
    __shared__ float S[52 * 53];

    const int tid = threadIdx.x;
    for (int i = tid; i < N_ * 32; i += 256) {
        int n = i >> 5, d = i & 31;
        qT[d * 56 + n] = qb[n * 768 + d];
        kT[d * 56 + n] = kb[n * 768 + d];
        V[n * 36 + d]  = vb[n * 768 + d];
    }
    __syncthreads();

    // QK^T: 13x13 grid of 4x4 register tiles (169 threads)
    if (tid < 169) {
        const int it = tid / 13, jt = tid % 13;
        const int i0 = it * 4, j0 = jt * 4;
        float acc[4][4] = {};
        #pragma unroll
        for (int d = 0; d < 32; d++) {
            float4 a = *(const float4*)&qT[d * 56 + i0];
            float4 bb = *(const float4*)&kT[d * 56 + j0];
            float ar[4] = {a.x, a.y, a.z, a.w};
            float br[4] = {bb.x, bb.y, bb.z, bb.w};
            #pragma unroll
            for (int r = 0; r < 4; r++)
                #pragma unroll
                for (int c = 0; c < 4; c++)
                    acc[r][c] += ar[r] * br[c];
        }
        const float* __restrict__ mrow = mask + (size_t)(b & (NW_ - 1)) * (N_ * N_);
        #pragma unroll
        for (int r = 0; r < 4; r++) {
            int i = i0 + r;
            if (i >= N_) break;
            #pragma unroll
            for (int c = 0; c < 4; c++) {
                int j = j0 + c;
                if (j >= N_) continue;
                S[i * 53 + j] = acc[r][c]
                    + bias_table[rel_idx[i * N_ + j] * H_ + h] + mrow[i * N_ + j];
            }
        }
    }
    __syncthreads();

    // softmax: one warp per row strip
    {
        const int w = tid >> 5, lane = tid & 31;
        for (int r = w; r < N_; r += 8) {
            float* row = &S[r * 53];
            float v1 = row[lane];
            float v2 = (lane + 32 < N_) ? row[lane + 32] : -1e30f;
            float mx = fmaxf(v1, v2);
            #pragma unroll
            for (int o = 16; o; o >>= 1) mx = fmaxf(mx, __shfl_xor_sync(~0u, mx, o));
            float e1 = __expf(v1 - mx);
            float e2 = (lane + 32 < N_) ? __expf(v2 - mx) : 0.f;
            float s = e1 + e2;
            #pragma unroll
            for (int o = 16; o; o >>= 1) s += __shfl_xor_sync(~0u, s, o);
            float inv = 1.f / s;
            row[lane] = e1 * inv;
            if (lane + 32 < N_) row[lane + 32] = e2 * inv;
        }
    }
    __syncthreads();

    // PV: 13x8 grid of 4(i)x4(d) tiles (104 threads)
    if (tid < 104) {
        const int it = tid >> 3, dt = tid & 7;
        const int i0 = it * 4, d0 = dt * 4;
        float o[4][4] = {};
        for (int j = 0; j < N_; j++) {
            float4 vv = *(const float4*)&V[j * 36 + d0];
            float vr[4] = {vv.x, vv.y, vv.z, vv.w};
            #pragma unroll
            for (int r = 0; r < 4; r++) {
                float pr = S[(i0 + r) * 53 + j];
                #pragma unroll
                for (int c = 0; c < 4; c++) o[r][c] += pr * vr[c];
            }
        }
        #pragma unroll
        for (int r = 0; r < 4; r++) {
            int i = i0 + r;
            if (i >= N_) break;
            __half* dst = &g_aob[p][((size_t)b * N_ + i) * KSP + h * 32 + d0];
            #pragma unroll
            for (int c = 0; c < 4; c++) {
                float v = o[r][c];
                __half hi = __float2half_rn(v);
                __half lo = __float2half_rn(v - __half2float(hi));
                dst[c] = hi;
                dst[256 + c] = lo;
            }
        }
    }
}

// ---------------- host launcher ----------------
extern "C" void kernel_launch(void* const* d_in, const int* in_sizes, int n_in,
                              void* d_out, int out_size)
{
    const float* x          = (const float*)d_in[0];
    const float* rgb        = (const float*)d_in[1];
    const float* mask       = (const float*)d_in[2];
    const float* w_qkv      = (const float*)d_in[3];
    const float* b_qkv      = (const float*)d_in[4];
    const float* w_qkv_rgb  = (const float*)d_in[5];
    const float* b_qkv_rgb  = (const float*)d_in[6];
    const float* bias_table = (const float*)d_in[7];
    const float* w_proj     = (const float*)d_in[8];
    const float* b_proj     = (const float*)d_in[9];
    const float* w_proj_rgb = (const float*)d_in[10];
    const float* b_proj_rgb = (const float*)d_in[11];
    const int*   rel_idx    = (const int*)d_in[12];
    float* out = (float*)d_out;

    cudaFuncSetAttribute(qkv_hmma,  cudaFuncAttributeMaxDynamicSharedMemorySize, SMEM_SZ);
    cudaFuncSetAttribute(proj_hmma, cudaFuncAttributeMaxDynamicSharedMemorySize, SMEM_SZ);

    conv_w<<<dim3(768, 4), 256>>>(w_qkv, w_qkv_rgb, w_proj, w_proj_rgb);
    conv_in<<<dim3(MT, 2), 256>>>(x, rgb);

    qkv_hmma<<<dim3(768 / BN, MT / BM, 2), 256, SMEM_SZ>>>(b_qkv, b_qkv_rgb);

    attn_kernel<<<dim3(B_, H_, 2), 256>>>(mask, bias_table, rel_idx);

    proj_hmma<<<dim3(256 / BN, MT / BM, 2), 256, SMEM_SZ>>>(b_proj, b_proj_rgb, out);
}

// round 6
// speedup vs baseline: 3.8473x; 1.1138x over previous
#include <cuda_runtime.h>
#include <cuda_fp16.h>
#include <cstdint>

#define B_  4096
#define N_  49
#define H_  8
#define NW_ 64
#define MT  (B_ * N_)              // 200704 rows
#define KSP 512                    // 2-term split K (2 * 256)
#define SZ_AO ((size_t)MT * 256)
#define NN2 (N_ * N_)              // 2401

#define SCALE_F 0.17677669529663687f

// ---------------- scratch (device globals; no runtime alloc) ----------------
__device__ __half g_A[2][(size_t)MT * KSP];     // input split [hi, lo] fp16
__device__ __half g_Wqkv[2][768 * 256];         // Wt[n][k] fp16
__device__ __half g_Wproj[2][256 * 256];
__device__ float  g_lin[2][(size_t)MT * 768];   // qkv linear out (q|k|v)
__device__ __half g_aob[2][(size_t)MT * KSP];   // attn out split [hi, lo]
__device__ float  g_bm[NW_ * H_ * NN2];         // combined bias+mask [w][h][i*49+j]

// ---------------- GEMM config ----------------
#define BM 128
#define BN 128
#define SA_STR 40
#define SB_STR 264
#define NCH 16

struct GSmem {
    __align__(16) __half B[BN * SB_STR];
    __align__(16) __half A[4][BM * SA_STR];
};
#define SMEM_SZ ((int)sizeof(GSmem))

__device__ __forceinline__ void cp16(uint32_t dst, const void* src) {
    asm volatile("cp.async.cg.shared.global [%0], [%1], 16;" :: "r"(dst), "l"(src));
}
__device__ __forceinline__ void cp_commit() {
    asm volatile("cp.async.commit_group;" ::: "memory");
}
template<int NN> __device__ __forceinline__ void cp_wait() {
    asm volatile("cp.async.wait_group %0;" :: "n"(NN) : "memory");
}

__device__ __forceinline__ void mma16816(float* d, const uint32_t* a, const uint32_t* b) {
    asm volatile(
        "mma.sync.aligned.m16n8k16.row.col.f32.f16.f16.f32 "
        "{%0,%1,%2,%3}, {%4,%5,%6,%7}, {%8,%9}, {%0,%1,%2,%3};"
        : "+f"(d[0]), "+f"(d[1]), "+f"(d[2]), "+f"(d[3])
        : "r"(a[0]), "r"(a[1]), "r"(a[2]), "r"(a[3]), "r"(b[0]), "r"(b[1]));
}

__device__ __forceinline__ void gemm_main(
    GSmem& sm, const __half* __restrict__ A, const __half* __restrict__ W,
    int bm, int bn, float acc[4][4][4])
{
    const int tid = threadIdx.x;
    const uint32_t sB = (uint32_t)__cvta_generic_to_shared(sm.B);
    const uint32_t sA = (uint32_t)__cvta_generic_to_shared(sm.A);

    #pragma unroll
    for (int i = 0; i < 16; i++) {
        int idx = tid + i * 256;
        int r = idx >> 5, g = idx & 31;
        cp16(sB + (uint32_t)(r * SB_STR + g * 8) * 2,
             W + (size_t)(bn + r) * 256 + g * 8);
    }
    cp_commit();

    auto issueA = [&](int c) {
        uint32_t dst = sA + (uint32_t)((c & 3) * BM * SA_STR) * 2;
        #pragma unroll
        for (int i = 0; i < 2; i++) {
            int idx = tid + i * 256;
            int r = idx >> 2, g = idx & 3;
            cp16(dst + (uint32_t)(r * SA_STR + g * 8) * 2,
                 A + (size_t)(bm + r) * KSP + c * 32 + g * 8);
        }
        cp_commit();
    };
    issueA(0); issueA(1); issueA(2);

    const int lane = tid & 31;
    const int wm = (tid >> 5) & 1, wn = tid >> 6;
    const int fr = lane >> 2, fq = (lane & 3) * 2;

    auto compute = [&](int c) {
        const __half* a_s = sm.A[c & 3];
        const __half* b_s = sm.B + (c & 7) * 32;
        #pragma unroll
        for (int ks = 0; ks < 2; ks++) {
            const int kb = ks * 16;
            uint32_t af[4][4], bf[4][2];
            #pragma unroll
            for (int mt = 0; mt < 4; mt++) {
                const __half* p = &a_s[(wm * 64 + mt * 16 + fr) * SA_STR + kb + fq];
                af[mt][0] = *(const uint32_t*)p;
                af[mt][1] = *(const uint32_t*)(p + 8 * SA_STR);
                af[mt][2] = *(const uint32_t*)(p + 8);
                af[mt][3] = *(const uint32_t*)(p + 8 * SA_STR + 8);
            }
            #pragma unroll
            for (int nt = 0; nt < 4; nt++) {
                const __half* p = &b_s[(wn * 32 + nt * 8 + fr) * SB_STR + kb + fq];
                bf[nt][0] = *(const uint32_t*)p;
                bf[nt][1] = *(const uint32_t*)(p + 8);
            }
            #pragma unroll
            for (int mt = 0; mt < 4; mt++)
                #pragma unroll
                for (int nt = 0; nt < 4; nt++)
                    mma16816(acc[mt][nt], af[mt], bf[nt]);
        }
    };

    for (int c = 0; c < 13; c++) {
        cp_wait<2>();
        __syncthreads();
        issueA(c + 3);
        compute(c);
    }
    cp_wait<2>(); __syncthreads(); compute(13);
    cp_wait<1>(); __syncthreads(); compute(14);
    cp_wait<0>(); __syncthreads(); compute(15);
}

// ---------------- GEMM kernels ----------------
__global__ __launch_bounds__(256, 2) void qkv_hmma(
    const float* __restrict__ b0, const float* __restrict__ b1)
{
    extern __shared__ char smem_raw[];
    GSmem& sm = *(GSmem*)smem_raw;
    const int stream = blockIdx.z;
    const int bn = blockIdx.x * BN;
    const int bm = blockIdx.y * BM;

    float acc[4][4][4] = {};
    gemm_main(sm, g_A[stream], g_Wqkv[stream], bm, bn, acc);

    const float* __restrict__ bias = stream ? b1 : b0;
    float* __restrict__ O = g_lin[stream];
    const int lane = threadIdx.x & 31;
    const int wm = (threadIdx.x >> 5) & 1, wn = threadIdx.x >> 6;
    const float sc = (bn < 256) ? SCALE_F : 1.0f;

    #pragma unroll
    for (int mt = 0; mt < 4; mt++) {
        const int r = bm + wm * 64 + mt * 16 + (lane >> 2);
        #pragma unroll
        for (int nt = 0; nt < 4; nt++) {
            const int col = bn + wn * 32 + nt * 8 + (lane & 3) * 2;
            const float bx = bias[col], by = bias[col + 1];
            float2 v0 = { (acc[mt][nt][0] + bx) * sc, (acc[mt][nt][1] + by) * sc };
            float2 v1 = { (acc[mt][nt][2] + bx) * sc, (acc[mt][nt][3] + by) * sc };
            *(float2*)&O[(size_t)r * 768 + col]       = v0;
            *(float2*)&O[(size_t)(r + 8) * 768 + col] = v1;
        }
    }
}

__global__ __launch_bounds__(256, 2) void proj_hmma(
    const float* __restrict__ bp0, const float* __restrict__ bp1,
    float* __restrict__ out)
{
    extern __shared__ char smem_raw[];
    GSmem& sm = *(GSmem*)smem_raw;
    const int p = blockIdx.z;
    const int bn = blockIdx.x * BN;
    const int bm = blockIdx.y * BM;

    float acc[4][4][4] = {};
    gemm_main(sm, g_aob[p], g_Wproj[p], bm, bn, acc);

    const float* __restrict__ bias = p ? bp1 : bp0;
    float* __restrict__ O = out + (size_t)p * SZ_AO;
    const int lane = threadIdx.x & 31;
    const int wm = (threadIdx.x >> 5) & 1, wn = threadIdx.x >> 6;

    #pragma unroll
    for (int mt = 0; mt < 4; mt++) {
        const int r = bm + wm * 64 + mt * 16 + (lane >> 2);
        #pragma unroll
        for (int nt = 0; nt < 4; nt++) {
            const int col = bn + wn * 32 + nt * 8 + (lane & 3) * 2;
            const float bx = bias[col], by = bias[col + 1];
            float2 v0 = { acc[mt][nt][0] + bx, acc[mt][nt][1] + by };
            float2 v1 = { acc[mt][nt][2] + bx, acc[mt][nt][3] + by };
            *(float2*)&O[(size_t)r * 256 + col]       = v0;
            *(float2*)&O[(size_t)(r + 8) * 256 + col] = v1;
        }
    }
}

// ---------------- conversion / precompute kernels ----------------
__global__ __launch_bounds__(256) void conv_in(
    const float* __restrict__ x, const float* __restrict__ rgb)
{
    const int s = blockIdx.y;
    const float* __restrict__ src = s ? rgb : x;
    const size_t m = blockIdx.x;
    const int k = threadIdx.x;
    float v = src[m * 256 + k];
    __half hi = __float2half_rn(v);
    __half lo = __float2half_rn(v - __half2float(hi));
    g_A[s][m * KSP + k] = hi;
    g_A[s][m * KSP + 256 + k] = lo;
}

__global__ __launch_bounds__(256) void conv_w(
    const float* __restrict__ w_qkv, const float* __restrict__ w_qkv_rgb,
    const float* __restrict__ w_proj, const float* __restrict__ w_proj_rgb)
{
    const int which = blockIdx.y;
    const float* src; __half* dst; int NC;
    switch (which) {
        case 0: src = w_qkv;       dst = g_Wqkv[0];  NC = 768; break;
        case 1: src = w_qkv_rgb;   dst = g_Wqkv[1];  NC = 768; break;
        case 2: src = w_proj;      dst = g_Wproj[0]; NC = 256; break;
        default: src = w_proj_rgb; dst = g_Wproj[1]; NC = 256; break;
    }
    int idx = blockIdx.x * 256 + threadIdx.x;
    if (idx >= 256 * NC) return;
    int k = idx / NC, n = idx % NC;
    dst[(size_t)n * 256 + k] = __float2half_rn(src[idx]);
}

// combined bias+mask: g_bm[(w*8+h)*2401 + idx] = bias_table[rel_idx[idx]*8+h] + mask[w][idx]
__global__ __launch_bounds__(256) void prep_bm(
    const float* __restrict__ mask, const float* __restrict__ bias_table,
    const int* __restrict__ rel_idx)
{
    const int w = blockIdx.x, h = blockIdx.y;
    float* __restrict__ dst = g_bm + (size_t)(w * H_ + h) * NN2;
    const float* __restrict__ msk = mask + (size_t)w * NN2;
    for (int idx = threadIdx.x; idx < NN2; idx += 256)
        dst[idx] = bias_table[rel_idx[idx] * H_ + h] + msk[idx];
}

// ---------------- fused attention (fp32, register-blocked) ----------------
__global__ __launch_bounds__(192) void attn_kernel()
{
    const int b = blockIdx.x, h = blockIdx.y, p = blockIdx.z;
    const int qs = p ^ 1, kv = p;
    const float* __restrict__ qb = g_lin[qs] + (size_t)b * N_ * 768 + h * 32;
    const float* __restrict__ kb = g_lin[kv] + (size_t)b * N_ * 768 + 256 + h * 32;
    const float* __restrict__ vb = g_lin[kv] + (size_t)b * N_ * 768 + 512 + h * 32;
    const float* __restrict__ bm = g_bm + (size_t)((b & (NW_ - 1)) * H_ + h) * NN2;

    __shared__ float qT[32 * 56];   // [d][n]
    __shared__ float kT[32 * 56];
    __shared__ float V[N_ * 36];    // [n][d]
    __shared__ float S[52 * 56];    // padded to 52 rows: PV tile reads rows 49-51

    const int tid = threadIdx.x;
    for (int i = tid; i < N_ * 32; i += 192) {
        int n = i >> 5, d = i & 31;
        qT[d * 56 + n] = qb[n * 768 + d];
        kT[d * 56 + n] = kb[n * 768 + d];
        V[n * 36 + d]  = vb[n * 768 + d];
    }
    // zero the 3 padding rows of S so the overrun tile accumulates finite values
    for (int i = tid; i < 3 * 56; i += 192) S[49 * 56 + i] = 0.f;
    __syncthreads();

    // QK^T + combined bias/mask: 13x13 grid of 4x4 tiles
    if (tid < 169) {
        const int it = tid / 13, jt = tid - (tid / 13) * 13;
        const int i0 = it * 4, j0 = jt * 4;
        float acc[4][4] = {};
        #pragma unroll
        for (int d = 0; d < 32; d++) {
            float4 a  = *(const float4*)&qT[d * 56 + i0];
            float4 bb = *(const float4*)&kT[d * 56 + j0];
            float ar[4] = {a.x, a.y, a.z, a.w};
            float br[4] = {bb.x, bb.y, bb.z, bb.w};
            #pragma unroll
            for (int r = 0; r < 4; r++)
                #pragma unroll
                for (int c = 0; c < 4; c++)
                    acc[r][c] += ar[r] * br[c];
        }
        #pragma unroll
        for (int r = 0; r < 4; r++) {
            int i = i0 + r;
            if (i >= N_) break;
            #pragma unroll
            for (int c = 0; c < 4; c++) {
                int j = j0 + c;
                if (j >= N_) continue;
                S[i * 56 + j] = acc[r][c] + bm[i * N_ + j];
            }
        }
    }
    __syncthreads();

    // softmax: 6 warps stride rows
    {
        const int w = tid >> 5, lane = tid & 31;
        for (int r = w; r < N_; r += 6) {
            float* row = &S[r * 56];
            float v1 = row[lane];
            float v2 = (lane + 32 < N_) ? row[lane + 32] : -1e30f;
            float mx = fmaxf(v1, v2);
            #pragma unroll
            for (int o = 16; o; o >>= 1) mx = fmaxf(mx, __shfl_xor_sync(~0u, mx, o));
            float e1 = __expf(v1 - mx);
            float e2 = (lane + 32 < N_) ? __expf(v2 - mx) : 0.f;
            float s = e1 + e2;
            #pragma unroll
            for (int o = 16; o; o >>= 1) s += __shfl_xor_sync(~0u, s, o);
            float inv = 1.f / s;
            row[lane] = e1 * inv;
            if (lane + 32 < N_) row[lane + 32] = e2 * inv;
        }
    }
    __syncthreads();

    // PV: 13(i) x 16(d) grid of 4x2 tiles = 208 over 192 threads
    for (int t = tid; t < 208; t += 192) {
        const int it = t >> 4, dt = t & 15;
        const int i0 = it * 4, d0 = dt * 2;
        float o[4][2] = {};
        for (int j = 0; j < N_; j++) {
            float2 vv = *(const float2*)&V[j * 36 + d0];
            #pragma unroll
            for (int r = 0; r < 4; r++) {
                float pr = S[(i0 + r) * 56 + j];
                o[r][0] += pr * vv.x;
                o[r][1] += pr * vv.y;
            }
        }
        #pragma unroll
        for (int r = 0; r < 4; r++) {
            int i = i0 + r;
            if (i >= N_) break;
            __half* dst = &g_aob[p][((size_t)b * N_ + i) * KSP + h * 32 + d0];
            __half h0 = __float2half_rn(o[r][0]);
            __half h1 = __float2half_rn(o[r][1]);
            __half l0 = __float2half_rn(o[r][0] - __half2float(h0));
            __half l1 = __float2half_rn(o[r][1] - __half2float(h1));
            *(__half2*)dst         = __halves2half2(h0, h1);
            *(__half2*)(dst + 256) = __halves2half2(l0, l1);
        }
    }
}

// ---------------- host launcher ----------------
extern "C" void kernel_launch(void* const* d_in, const int* in_sizes, int n_in,
                              void* d_out, int out_size)
{
    const float* x          = (const float*)d_in[0];
    const float* rgb        = (const float*)d_in[1];
    const float* mask       = (const float*)d_in[2];
    const float* w_qkv      = (const float*)d_in[3];
    const float* b_qkv      = (const float*)d_in[4];
    const float* w_qkv_rgb  = (const float*)d_in[5];
    const float* b_qkv_rgb  = (const float*)d_in[6];
    const float* bias_table = (const float*)d_in[7];
    const float* w_proj     = (const float*)d_in[8];
    const float* b_proj     = (const float*)d_in[9];
    const float* w_proj_rgb = (const float*)d_in[10];
    const float* b_proj_rgb = (const float*)d_in[11];
    const int*   rel_idx    = (const int*)d_in[12];
    float* out = (float*)d_out;

    cudaFuncSetAttribute(qkv_hmma,  cudaFuncAttributeMaxDynamicSharedMemorySize, SMEM_SZ);
    cudaFuncSetAttribute(proj_hmma, cudaFuncAttributeMaxDynamicSharedMemorySize, SMEM_SZ);

    conv_w<<<dim3(768, 4), 256>>>(w_qkv, w_qkv_rgb, w_proj, w_proj_rgb);
    prep_bm<<<dim3(NW_, H_), 256>>>(mask, bias_table, rel_idx);
    conv_in<<<dim3(MT, 2), 256>>>(x, rgb);

    qkv_hmma<<<dim3(768 / BN, MT / BM, 2), 256, SMEM_SZ>>>(b_qkv, b_qkv_rgb);

    attn_kernel<<<dim3(B_, H_, 2), 192>>>();

    proj_hmma<<<dim3(256 / BN, MT / BM, 2), 256, SMEM_SZ>>>(b_proj, b_proj_rgb, out);
}

// round 7
// speedup vs baseline: 4.1661x; 1.0829x over previous
#include <cuda_runtime.h>
#include <cuda_fp16.h>
#include <cstdint>

#define B_  4096
#define N_  49
#define H_  8
#define NW_ 64
#define MT  (B_ * N_)              // 200704 rows
#define KSP 512                    // 2-term split K (2 * 256)
#define SZ_AO ((size_t)MT * 256)
#define NN2 (N_ * N_)              // 2401

#define SCALE_F 0.17677669529663687f

// ---------------- scratch (device globals; no runtime alloc) ----------------
__device__ __half g_A[2][(size_t)MT * KSP];     // input split [hi, lo] fp16
__device__ __half g_Wqkv[2][768 * 256];         // Wt[n][k] fp16
__device__ __half g_Wproj[2][256 * 256];
__device__ float  g_lin[2][(size_t)MT * 768];   // qkv linear out (q|k|v)
__device__ __half g_aob[2][(size_t)MT * KSP];   // attn out split [hi, lo]
__device__ float  g_bm[NW_ * H_ * NN2];         // combined bias+mask

// ---------------- GEMM config ----------------
#define BM 128
#define BN 128
#define SA_STR 40
#define SB_STR 264

struct GSmem {
    __align__(16) __half B[BN * SB_STR];
    __align__(16) __half A[4][BM * SA_STR];
};
#define SMEM_SZ ((int)sizeof(GSmem))

__device__ __forceinline__ void cp16(uint32_t dst, const void* src) {
    asm volatile("cp.async.cg.shared.global [%0], [%1], 16;" :: "r"(dst), "l"(src));
}
__device__ __forceinline__ void cp_commit() {
    asm volatile("cp.async.commit_group;" ::: "memory");
}
template<int NN> __device__ __forceinline__ void cp_wait() {
    asm volatile("cp.async.wait_group %0;" :: "n"(NN) : "memory");
}

__device__ __forceinline__ void mma16816(float* d, const uint32_t* a, const uint32_t* b) {
    asm volatile(
        "mma.sync.aligned.m16n8k16.row.col.f32.f16.f16.f32 "
        "{%0,%1,%2,%3}, {%4,%5,%6,%7}, {%8,%9}, {%0,%1,%2,%3};"
        : "+f"(d[0]), "+f"(d[1]), "+f"(d[2]), "+f"(d[3])
        : "r"(a[0]), "r"(a[1]), "r"(a[2]), "r"(a[3]), "r"(b[0]), "r"(b[1]));
}

#define LDSM_X4(r, addr)                                                     \
    asm volatile("ldmatrix.sync.aligned.m8n8.x4.shared.b16 {%0,%1,%2,%3}, [%4];" \
        : "=r"((r)[0]), "=r"((r)[1]), "=r"((r)[2]), "=r"((r)[3]) : "r"(addr))

__device__ __forceinline__ void gemm_main(
    GSmem& sm, const __half* __restrict__ A, const __half* __restrict__ W,
    int bm, int bn, float acc[4][4][4])
{
    const int tid = threadIdx.x;
    const uint32_t sB = (uint32_t)__cvta_generic_to_shared(sm.B);
    const uint32_t sA = (uint32_t)__cvta_generic_to_shared(sm.A);

    #pragma unroll
    for (int i = 0; i < 16; i++) {
        int idx = tid + i * 256;
        int r = idx >> 5, g = idx & 31;
        cp16(sB + (uint32_t)(r * SB_STR + g * 8) * 2,
             W + (size_t)(bn + r) * 256 + g * 8);
    }
    cp_commit();

    auto issueA = [&](int c) {
        uint32_t dst = sA + (uint32_t)((c & 3) * BM * SA_STR) * 2;
        #pragma unroll
        for (int i = 0; i < 2; i++) {
            int idx = tid + i * 256;
            int r = idx >> 2, g = idx & 3;
            cp16(dst + (uint32_t)(r * SA_STR + g * 8) * 2,
                 A + (size_t)(bm + r) * KSP + c * 32 + g * 8);
        }
        cp_commit();
    };
    issueA(0); issueA(1); issueA(2);

    const int lane = tid & 31;
    const int wm = (tid >> 5) & 1, wn = tid >> 6;

    // ldmatrix lane address components (canonical m16n8k16 fragment mapping)
    const int a_row = wm * 64 + (lane & 7) + ((lane >> 3) & 1) * 8;  // + mt*16
    const int a_col = (lane >> 4) * 8;                                // + kb
    const int b_row = wn * 32 + (lane >> 4) * 8 + (lane & 7);         // + pair*16
    const int b_col = ((lane >> 3) & 1) * 8;                          // + kb

    auto compute = [&](int c) {
        const uint32_t aBase = sA + (uint32_t)((c & 3) * BM * SA_STR) * 2;
        const uint32_t bBase = sB + (uint32_t)((c & 7) * 32) * 2;
        #pragma unroll
        for (int ks = 0; ks < 2; ks++) {
            const int kb = ks * 16;
            uint32_t af[4][4], bf[2][4];
            #pragma unroll
            for (int mt = 0; mt < 4; mt++)
                LDSM_X4(af[mt],
                        aBase + (uint32_t)((a_row + mt * 16) * SA_STR + kb + a_col) * 2);
            #pragma unroll
            for (int pr = 0; pr < 2; pr++)
                LDSM_X4(bf[pr],
                        bBase + (uint32_t)((b_row + pr * 16) * SB_STR + kb + b_col) * 2);
            #pragma unroll
            for (int mt = 0; mt < 4; mt++)
                #pragma unroll
                for (int nt = 0; nt < 4; nt++)
                    mma16816(acc[mt][nt], af[mt], &bf[nt >> 1][(nt & 1) * 2]);
        }
    };

    for (int c = 0; c < 13; c++) {
        cp_wait<2>();
        __syncthreads();
        issueA(c + 3);
        compute(c);
    }
    cp_wait<2>(); __syncthreads(); compute(13);
    cp_wait<1>(); __syncthreads(); compute(14);
    cp_wait<0>(); __syncthreads(); compute(15);
}

// ---------------- GEMM kernels ----------------
__global__ __launch_bounds__(256, 2) void qkv_hmma(
    const float* __restrict__ b0, const float* __restrict__ b1)
{
    extern __shared__ char smem_raw[];
    GSmem& sm = *(GSmem*)smem_raw;
    const int stream = blockIdx.z;
    const int bn = blockIdx.x * BN;
    const int bm = blockIdx.y * BM;

    float acc[4][4][4] = {};
    gemm_main(sm, g_A[stream], g_Wqkv[stream], bm, bn, acc);

    const float* __restrict__ bias = stream ? b1 : b0;
    float* __restrict__ O = g_lin[stream];
    const int lane = threadIdx.x & 31;
    const int wm = (threadIdx.x >> 5) & 1, wn = threadIdx.x >> 6;
    const float sc = (bn < 256) ? SCALE_F : 1.0f;

    #pragma unroll
    for (int mt = 0; mt < 4; mt++) {
        const int r = bm + wm * 64 + mt * 16 + (lane >> 2);
        #pragma unroll
        for (int nt = 0; nt < 4; nt++) {
            const int col = bn + wn * 32 + nt * 8 + (lane & 3) * 2;
            const float bx = bias[col], by = bias[col + 1];
            float2 v0 = { (acc[mt][nt][0] + bx) * sc, (acc[mt][nt][1] + by) * sc };
            float2 v1 = { (acc[mt][nt][2] + bx) * sc, (acc[mt][nt][3] + by) * sc };
            *(float2*)&O[(size_t)r * 768 + col]       = v0;
            *(float2*)&O[(size_t)(r + 8) * 768 + col] = v1;
        }
    }
}

__global__ __launch_bounds__(256, 2) void proj_hmma(
    const float* __restrict__ bp0, const float* __restrict__ bp1,
    float* __restrict__ out)
{
    extern __shared__ char smem_raw[];
    GSmem& sm = *(GSmem*)smem_raw;
    const int p = blockIdx.z;
    const int bn = blockIdx.x * BN;
    const int bm = blockIdx.y * BM;

    float acc[4][4][4] = {};
    gemm_main(sm, g_aob[p], g_Wproj[p], bm, bn, acc);

    const float* __restrict__ bias = p ? bp1 : bp0;
    float* __restrict__ O = out + (size_t)p * SZ_AO;
    const int lane = threadIdx.x & 31;
    const int wm = (threadIdx.x >> 5) & 1, wn = threadIdx.x >> 6;

    #pragma unroll
    for (int mt = 0; mt < 4; mt++) {
        const int r = bm + wm * 64 + mt * 16 + (lane >> 2);
        #pragma unroll
        for (int nt = 0; nt < 4; nt++) {
            const int col = bn + wn * 32 + nt * 8 + (lane & 3) * 2;
            const float bx = bias[col], by = bias[col + 1];
            float2 v0 = { acc[mt][nt][0] + bx, acc[mt][nt][1] + by };
            float2 v1 = { acc[mt][nt][2] + bx, acc[mt][nt][3] + by };
            *(float2*)&O[(size_t)r * 256 + col]       = v0;
            *(float2*)&O[(size_t)(r + 8) * 256 + col] = v1;
        }
    }
}

// ---------------- conversion / precompute kernels ----------------
__global__ __launch_bounds__(256) void conv_in(
    const float* __restrict__ x, const float* __restrict__ rgb)
{
    const int s = blockIdx.y;
    const float* __restrict__ src = s ? rgb : x;
    const size_t m = blockIdx.x;
    const int k = threadIdx.x;
    float v = src[m * 256 + k];
    __half hi = __float2half_rn(v);
    __half lo = __float2half_rn(v - __half2float(hi));
    g_A[s][m * KSP + k] = hi;
    g_A[s][m * KSP + 256 + k] = lo;
}

__global__ __launch_bounds__(256) void conv_w(
    const float* __restrict__ w_qkv, const float* __restrict__ w_qkv_rgb,
    const float* __restrict__ w_proj, const float* __restrict__ w_proj_rgb)
{
    const int which = blockIdx.y;
    const float* src; __half* dst; int NC;
    switch (which) {
        case 0: src = w_qkv;       dst = g_Wqkv[0];  NC = 768; break;
        case 1: src = w_qkv_rgb;   dst = g_Wqkv[1];  NC = 768; break;
        case 2: src = w_proj;      dst = g_Wproj[0]; NC = 256; break;
        default: src = w_proj_rgb; dst = g_Wproj[1]; NC = 256; break;
    }
    int idx = blockIdx.x * 256 + threadIdx.x;
    if (idx >= 256 * NC) return;
    int k = idx / NC, n = idx % NC;
    dst[(size_t)n * 256 + k] = __float2half_rn(src[idx]);
}

__global__ __launch_bounds__(256) void prep_bm(
    const float* __restrict__ mask, const float* __restrict__ bias_table,
    const int* __restrict__ rel_idx)
{
    const int w = blockIdx.x, h = blockIdx.y;
    float* __restrict__ dst = g_bm + (size_t)(w * H_ + h) * NN2;
    const float* __restrict__ msk = mask + (size_t)w * NN2;
    for (int idx = threadIdx.x; idx < NN2; idx += 256)
        dst[idx] = bias_table[rel_idx[idx] * H_ + h] + msk[idx];
}

// ---------------- fused attention (fp32, register-blocked) ----------------
__global__ __launch_bounds__(192) void attn_kernel()
{
    const int b = blockIdx.x, h = blockIdx.y, p = blockIdx.z;
    const int qs = p ^ 1, kv = p;
    const float* __restrict__ qb = g_lin[qs] + (size_t)b * N_ * 768 + h * 32;
    const float* __restrict__ kb = g_lin[kv] + (size_t)b * N_ * 768 + 256 + h * 32;
    const float* __restrict__ vb = g_lin[kv] + (size_t)b * N_ * 768 + 512 + h * 32;
    const float* __restrict__ bm = g_bm + (size_t)((b & (NW_ - 1)) * H_ + h) * NN2;

    __shared__ float qT[32 * 56];   // [d][n]
    __shared__ float kT[32 * 56];
    __shared__ float V[N_ * 36];    // [n][d]
    __shared__ float S[52 * 56];    // padded: PV tile reads rows 49-51

    const int tid = threadIdx.x;
    for (int i = tid; i < N_ * 32; i += 192) {
        int n = i >> 5, d = i & 31;
        qT[d * 56 + n] = qb[n * 768 + d];
        kT[d * 56 + n] = kb[n * 768 + d];
        V[n * 36 + d]  = vb[n * 768 + d];
    }
    for (int i = tid; i < 3 * 56; i += 192) S[49 * 56 + i] = 0.f;
    __syncthreads();

    if (tid < 169) {
        const int it = tid / 13, jt = tid - (tid / 13) * 13;
        const int i0 = it * 4, j0 = jt * 4;
        float acc[4][4] = {};
        #pragma unroll
        for (int d = 0; d < 32; d++) {
            float4 a  = *(const float4*)&qT[d * 56 + i0];
            float4 bb = *(const float4*)&kT[d * 56 + j0];
            float ar[4] = {a.x, a.y, a.z, a.w};
            float br[4] = {bb.x, bb.y, bb.z, bb.w};
            #pragma unroll
            for (int r = 0; r < 4; r++)
                #pragma unroll
                for (int c = 0; c < 4; c++)
                    acc[r][c] += ar[r] * br[c];
        }
        #pragma unroll
        for (int r = 0; r < 4; r++) {
            int i = i0 + r;
            if (i >= N_) break;
            #pragma unroll
            for (int c = 0; c < 4; c++) {
                int j = j0 + c;
                if (j >= N_) continue;
                S[i * 56 + j] = acc[r][c] + bm[i * N_ + j];
            }
        }
    }
    __syncthreads();

    {
        const int w = tid >> 5, lane = tid & 31;
        for (int r = w; r < N_; r += 6) {
            float* row = &S[r * 56];
            float v1 = row[lane];
            float v2 = (lane + 32 < N_) ? row[lane + 32] : -1e30f;
            float mx = fmaxf(v1, v2);
            #pragma unroll
            for (int o = 16; o; o >>= 1) mx = fmaxf(mx, __shfl_xor_sync(~0u, mx, o));
            float e1 = __expf(v1 - mx);
            float e2 = (lane + 32 < N_) ? __expf(v2 - mx) : 0.f;
            float s = e1 + e2;
            #pragma unroll
            for (int o = 16; o; o >>= 1) s += __shfl_xor_sync(~0u, s, o);
            float inv = 1.f / s;
            row[lane] = e1 * inv;
            if (lane + 32 < N_) row[lane + 32] = e2 * inv;
        }
    }
    __syncthreads();

    for (int t = tid; t < 208; t += 192) {
        const int it = t >> 4, dt = t & 15;
        const int i0 = it * 4, d0 = dt * 2;
        float o[4][2] = {};
        for (int j = 0; j < N_; j++) {
            float2 vv = *(const float2*)&V[j * 36 + d0];
            #pragma unroll
            for (int r = 0; r < 4; r++) {
                float pr = S[(i0 + r) * 56 + j];
                o[r][0] += pr * vv.x;
                o[r][1] += pr * vv.y;
            }
        }
        #pragma unroll
        for (int r = 0; r < 4; r++) {
            int i = i0 + r;
            if (i >= N_) break;
            __half* dst = &g_aob[p][((size_t)b * N_ + i) * KSP + h * 32 + d0];
            __half h0 = __float2half_rn(o[r][0]);
            __half h1 = __float2half_rn(o[r][1]);
            __half l0 = __float2half_rn(o[r][0] - __half2float(h0));
            __half l1 = __float2half_rn(o[r][1] - __half2float(h1));
            *(__half2*)dst         = __halves2half2(h0, h1);
            *(__half2*)(dst + 256) = __halves2half2(l0, l1);
        }
    }
}

// ---------------- host launcher ----------------
extern "C" void kernel_launch(void* const* d_in, const int* in_sizes, int n_in,
                              void* d_out, int out_size)
{
    const float* x          = (const float*)d_in[0];
    const float* rgb        = (const float*)d_in[1];
    const float* mask       = (const float*)d_in[2];
    const float* w_qkv      = (const float*)d_in[3];
    const float* b_qkv      = (const float*)d_in[4];
    const float* w_qkv_rgb  = (const float*)d_in[5];
    const float* b_qkv_rgb  = (const float*)d_in[6];
    const float* bias_table = (const float*)d_in[7];
    const float* w_proj     = (const float*)d_in[8];
    const float* b_proj     = (const float*)d_in[9];
    const float* w_proj_rgb = (const float*)d_in[10];
    const float* b_proj_rgb = (const float*)d_in[11];
    const int*   rel_idx    = (const int*)d_in[12];
    float* out = (float*)d_out;

    cudaFuncSetAttribute(qkv_hmma,  cudaFuncAttributeMaxDynamicSharedMemorySize, SMEM_SZ);
    cudaFuncSetAttribute(proj_hmma, cudaFuncAttributeMaxDynamicSharedMemorySize, SMEM_SZ);

    conv_w<<<dim3(768, 4), 256>>>(w_qkv, w_qkv_rgb, w_proj, w_proj_rgb);
    prep_bm<<<dim3(NW_, H_), 256>>>(mask, bias_table, rel_idx);
    conv_in<<<dim3(MT, 2), 256>>>(x, rgb);

    qkv_hmma<<<dim3(768 / BN, MT / BM, 2), 256, SMEM_SZ>>>(b_qkv, b_qkv_rgb);

    attn_kernel<<<dim3(B_, H_, 2), 192>>>();

    proj_hmma<<<dim3(256 / BN, MT / BM, 2), 256, SMEM_SZ>>>(b_proj, b_proj_rgb, out);
}